// round 15
// baseline (speedup 1.0000x reference)
#include <cuda_runtime.h>
#include <cuda_bf16.h>
#include <cstdint>
typedef unsigned short u16;
typedef uint32_t u32;

#define KH 20
#define PW 36            // plane pitch in u32
#define PWB 144          // plane pitch in bytes

__device__ u16 g_CtH[16*4096], g_CtL[16*4096];   // [al][fo][fi]
__device__ u16 g_WtH[16*4096], g_WtL[16*4096];   // [al][g][f]
__device__ float g_cb[16*64];

__device__ __forceinline__ u32 bf2(float a, float b){
    u32 r; asm("cvt.rn.bf16x2.f32 %0, %1, %2;" : "=r"(r) : "f"(b), "f"(a)); return r;
}
__device__ __forceinline__ void splitp(float a, float b, u32& hi, u32& lo){
    hi = bf2(a, b);
    float ha = __uint_as_float(hi << 16);
    float hb = __uint_as_float(hi & 0xFFFF0000u);
    lo = bf2(a - ha, b - hb);
}
__device__ __forceinline__ void splits(float v, u16& hs, u16& ls){
    u32 hi, lo;
    splitp(v, 0.f, hi, lo);
    hs = (u16)(hi & 0xFFFFu); ls = (u16)(lo & 0xFFFFu);
}
__device__ __forceinline__ u32 s2u(const void* p){
    u32 a; asm("{ .reg .u64 t; cvta.to.shared.u64 t, %1; cvt.u32.u64 %0, t; }" : "=r"(a) : "l"(p));
    return a;
}
#define BARP(id) asm volatile("bar.sync %0, 64;" :: "r"(id) : "memory")
#define MMAB(d, a, b) asm volatile( \
  "mma.sync.aligned.m16n8k16.row.col.f32.bf16.bf16.f32 " \
  "{%0,%1,%2,%3},{%4,%5,%6,%7},{%8,%9},{%0,%1,%2,%3};" \
  : "+f"((d)[0]),"+f"((d)[1]),"+f"((d)[2]),"+f"((d)[3]) \
  : "r"((a)[0]),"r"((a)[1]),"r"((a)[2]),"r"((a)[3]),"r"((b)[0]),"r"((b)[1]))
__device__ __forceinline__ void mma3(float* d, const u32* ah, const u32* al,
                                     const u32* bh, const u32* bl){
    MMAB(d, ah, bh); MMAB(d, al, bh); MMAB(d, ah, bl);
}
#define LDSM4(r, ad) asm volatile("ldmatrix.sync.aligned.m8n8.x4.shared.b16 {%0,%1,%2,%3}, [%4];" \
    : "=r"((r)[0]),"=r"((r)[1]),"=r"((r)[2]),"=r"((r)[3]) : "r"(ad))
#define LDSM2(r, ad) asm volatile("ldmatrix.sync.aligned.m8n8.x2.shared.b16 {%0,%1}, [%2];" \
    : "=r"((r)[0]),"=r"((r)[1]) : "r"(ad))
#define LDSM4T(r, ad) asm volatile("ldmatrix.sync.aligned.m8n8.x4.trans.shared.b16 {%0,%1,%2,%3}, [%4];" \
    : "=r"((r)[0]),"=r"((r)[1]),"=r"((r)[2]),"=r"((r)[3]) : "r"(ad))

// ---------------- precompute: grid (16, 4) ----------------
__global__ __launch_bounds__(256) void precompute_kernel(
    const float* __restrict__ Wq, const float* __restrict__ bq,
    const float* __restrict__ Wk, const float* __restrict__ Wt)
{
    __shared__ float sWq[64][65], sWk[64][65], sbq[64];
    int al = blockIdx.x, y = blockIdx.y;
    int a = al >> 2, l = al & 3;
    size_t wb = ((size_t)(7 + a) * 5 + l) * 4096;
    size_t bb = ((size_t)(7 + a) * 5 + l) * 64;
    int t = threadIdx.x;
    for (int i = t; i < 4096; i += 256) {
        sWq[i >> 6][i & 63] = Wq[wb + i];
        sWk[i >> 6][i & 63] = Wk[wb + i];
    }
#pragma unroll
    for (int it = 0; it < 4; it++) {
        int i = y*1024 + it*256 + t;
        u16 hs, ls;
        splits(Wt[wb + i], hs, ls);
        g_WtH[al*4096 + i] = hs; g_WtL[al*4096 + i] = ls;
    }
    if (t < 64) sbq[t] = bq[bb + t];
    __syncthreads();
    int tf = t & 15, fr = t >> 4;
    int fi = y*16 + fr;
    float acc[4] = {};
    for (int g = 0; g < 64; g++) {
        float qv = sWq[g][fi];
#pragma unroll
        for (int j = 0; j < 4; j++) acc[j] += qv * sWk[g][tf*4 + j];
    }
#pragma unroll
    for (int j = 0; j < 4; j++) {
        u16 hs, ls;
        splits(acc[j], hs, ls);
        int idx = al*4096 + (tf*4+j)*64 + fi;
        g_CtH[idx] = hs; g_CtL[idx] = ls;
    }
    if (y == 0 && t < 64) {
        float s = 0.f;
        for (int g = 0; g < 64; g++) s += sbq[g] * sWk[g][t];
        g_cb[al*64 + t] = s;
    }
}

// ---------------- fused attention ----------------
__global__ __launch_bounds__(256, 2) void attn_kernel(
    const float* __restrict__ X, const float* __restrict__ bt,
    float* __restrict__ out)
{
    extern __shared__ u32 sm[];
    u32* winH = sm;
    u32* winL = winH + 112*PW;
    u32* ctH  = winL + 112*PW;         // C^T planes (read-only after load)
    u32* ctL  = ctH + 64*PW;
    u32* uH   = ctL + 64*PW;           // U planes, later ctx
    u32* uL   = uH + 64*PW;
    u32* wgH  = uL + 64*PW;            // wgt planes
    u32* wgL  = wgH + 64*PW;
    float* sFlag = (float*)(wgL + 64*PW);  // 112
    float* sBt   = sFlag + 112;            // 64
    float* scb   = sBt + 64;               // 64
    float* redM  = scb + 64;               // 128 (row*2 + h)
    float* redS  = redM + 128;             // 128

    int bx = blockIdx.x;
    int st = bx & 31, b = (bx >> 5) & 3, al = bx >> 7;
    int a = al >> 2, l = al & 3;
    int s0 = st * 64;
    int t = threadIdx.x;
    int lane = t & 31;
    int gid = lane >> 2, tig = lane & 3;
    int w = t >> 5, mb = w & 3, h = w >> 2;
    int m0 = mb * 16;
    int barid = mb + 1;

    u32 bWinH = s2u(winH), bCtH = s2u(ctH), bUH = s2u(uH), bWgH = s2u(wgH);
    const u32 dWin = 112*PWB, dP = 64*PWB;

    const u32 offA  = (lane & 15)*PWB + ((lane >> 4) << 4);
    const u32 offBP = ((lane & 7) + ((lane & 16) >> 1))*PWB + ((lane & 8) << 1);
    const u32 offBS = (lane & 7)*PWB + ((lane & 8) << 1);
    const u32 offBT = (lane & 15)*PWB + (((lane & 16) >> 1) << 1);

    // ---- window load ----
#pragma unroll
    for (int it = 0; it < 7; it++) {
        int q = t + it*256;
        int r = q >> 4, c4 = q & 15;
        int sg = s0 - KH + r;
        float4 v = make_float4(0.f, 0.f, 0.f, 0.f);
        if (sg >= 0 && sg < 2048)
            v = *(const float4*)&X[(((size_t)b*2048 + sg)*4 + a)*64 + c4*4];
        u32 h01, l01, h23, l23;
        splitp(v.x, v.y, h01, l01);
        splitp(v.z, v.w, h23, l23);
        winH[r*PW + c4*2] = h01; winH[r*PW + c4*2 + 1] = h23;
        winL[r*PW + c4*2] = l01; winL[r*PW + c4*2 + 1] = l23;
        bool nz = (v.x != 0.f) | (v.y != 0.f) | (v.z != 0.f) | (v.w != 0.f);
        u32 m = __ballot_sync(0xFFFFFFFFu, nz);
        if (lane == 0)  sFlag[r] = (m & 0xFFFFu) ? 1.f : 0.f;
        if (lane == 16) sFlag[r] = (m >> 16)     ? 1.f : 0.f;
    }
    const u32* gCtH = (const u32*)g_CtH + al*2048;
    const u32* gCtL = (const u32*)g_CtL + al*2048;
#pragma unroll
    for (int it = 0; it < 8; it++) {
        int q = t + it*256;
        int r = q >> 5, c = q & 31;
        ctH[r*PW + c] = gCtH[q]; ctL[r*PW + c] = gCtL[q];
    }
    if (t < 64) {
        scb[t] = g_cb[al*64 + t];
        sBt[t] = bt[((7 + a)*5 + l)*64 + t];
    }
    __syncthreads();   // only full-CTA barrier; everything after is pair-local

    // ---- U = Xc*C + cb ----
    {
        float d[4][4] = {};
        u32 aB0[8], aB1[8], bhp[2][4], blp[2][4];
        u32 adA = bWinH + (KH + m0)*PWB + offA;
        LDSM4(aB0, adA); LDSM4(aB0+4, adA + dWin);
#pragma unroll
        for (int ks = 0; ks < 4; ks++) {
            int kB = ks*32;
            u32 adB0 = bCtH + (h*32)*PWB + offBP + kB;
            u32 adB1 = adB0 + 16*PWB;
            LDSM4(bhp[0], adB0); LDSM4(blp[0], adB0 + dP);
            LDSM4(bhp[1], adB1); LDSM4(blp[1], adB1 + dP);
            u32* cur = (ks & 1) ? aB1 : aB0;
            if (ks < 3) {
                u32* nxt = (ks & 1) ? aB0 : aB1;
                u32 adN = adA + kB + 32;
                LDSM4(nxt, adN); LDSM4(nxt+4, adN + dWin);
            }
#pragma unroll
            for (int p = 0; p < 2; p++) {
                mma3(d[p*2],   cur, cur+4, bhp[p],   blp[p]);
                mma3(d[p*2+1], cur, cur+4, bhp[p]+2, blp[p]+2);
            }
        }
#pragma unroll
        for (int nt = 0; nt < 4; nt++) {
            int c0 = h*32 + nt*8 + tig*2;
            float cb0 = scb[c0], cb1 = scb[c0+1];
            u32 hi, lo;
            splitp(d[nt][0] + cb0, d[nt][1] + cb1, hi, lo);
            uH[(m0+gid)*PW + c0/2] = hi; uL[(m0+gid)*PW + c0/2] = lo;
            splitp(d[nt][2] + cb0, d[nt][3] + cb1, hi, lo);
            uH[(m0+gid+8)*PW + c0/2] = hi; uL[(m0+gid+8)*PW + c0/2] = lo;
        }
    }
    BARP(barid);

    // ---- scores (kept in registers) + fragment softmax -> wgt planes ----
    {
        float d[4][4] = {};
        u32 aB0[8], aB1[8], bhp[2][4], blp[2][4];
        u32 adA = bUH + m0*PWB + offA;
        LDSM4(aB0, adA); LDSM4(aB0+4, adA + dP);
#pragma unroll
        for (int ks = 0; ks < 4; ks++) {
            int kB = ks*32;
            u32 adB0 = bWinH + (m0 + h*32)*PWB + offBP + kB;
            LDSM4(bhp[0], adB0); LDSM4(blp[0], adB0 + dWin);
            if (h == 0) {
                u32 adB1 = adB0 + 16*PWB;
                LDSM4(bhp[1], adB1); LDSM4(blp[1], adB1 + dWin);
            } else {
                u32 adB1 = bWinH + (m0 + 48)*PWB + offBS + kB;
                LDSM2(bhp[1], adB1); LDSM2(blp[1], adB1 + dWin);
            }
            u32* cur = (ks & 1) ? aB1 : aB0;
            if (ks < 3) {
                u32* nxt = (ks & 1) ? aB0 : aB1;
                u32 adN = adA + kB + 32;
                LDSM4(nxt, adN); LDSM4(nxt+4, adN + dP);
            }
            mma3(d[0], cur, cur+4, bhp[0],   blp[0]);
            mma3(d[1], cur, cur+4, bhp[0]+2, blp[0]+2);
            mma3(d[2], cur, cur+4, bhp[1],   blp[1]);
            if (h == 0) mma3(d[3], cur, cur+4, bhp[1]+2, blp[1]+2);
        }
        int nts = (h == 0) ? 4 : 3;
        float vv0[8], vv1[8];
        float m0v = -1e30f, m1v = -1e30f;
#pragma unroll
        for (int nt = 0; nt < 4; nt++) {
#pragma unroll
            for (int hf = 0; hf < 2; hf++) {
                int c = h*32 + nt*8 + tig*2 + hf;
                float v0 = -1e9f, v1 = -1e9f;
                if (nt < nts) {
                    float fl = sFlag[m0 + c];
                    v0 = d[nt][hf]   * 0.125f;
                    v1 = d[nt][2+hf] * 0.125f;
                    if (fl == 0.f) { v0 = -1e9f; v1 = -1e9f; }
                    if (c < gid   || c > gid + 40) v0 = -1e9f;
                    if (c < gid+8 || c > gid + 48) v1 = -1e9f;
                }
                vv0[nt*2+hf] = v0; vv1[nt*2+hf] = v1;
                m0v = fmaxf(m0v, v0); m1v = fmaxf(m1v, v1);
            }
        }
        m0v = fmaxf(m0v, __shfl_xor_sync(0xFFFFFFFFu, m0v, 1));
        m0v = fmaxf(m0v, __shfl_xor_sync(0xFFFFFFFFu, m0v, 2));
        m1v = fmaxf(m1v, __shfl_xor_sync(0xFFFFFFFFu, m1v, 1));
        m1v = fmaxf(m1v, __shfl_xor_sync(0xFFFFFFFFu, m1v, 2));
        float s0 = 0.f, s1 = 0.f;
#pragma unroll
        for (int i = 0; i < 8; i++) {
            s0 += __expf(vv0[i] - m0v);
            s1 += __expf(vv1[i] - m1v);
        }
        s0 += __shfl_xor_sync(0xFFFFFFFFu, s0, 1);
        s0 += __shfl_xor_sync(0xFFFFFFFFu, s0, 2);
        s1 += __shfl_xor_sync(0xFFFFFFFFu, s1, 1);
        s1 += __shfl_xor_sync(0xFFFFFFFFu, s1, 2);
        if (tig == 0) {
            redM[(m0+gid)*2 + h]   = m0v; redS[(m0+gid)*2 + h]   = s0;
            redM[(m0+gid+8)*2 + h] = m1v; redS[(m0+gid+8)*2 + h] = s1;
        }
        BARP(barid);
        float om0 = redM[(m0+gid)*2 + (1^h)],   os0 = redS[(m0+gid)*2 + (1^h)];
        float om1 = redM[(m0+gid+8)*2 + (1^h)], os1 = redS[(m0+gid+8)*2 + (1^h)];
        float M0 = fmaxf(m0v, om0);
        float M1 = fmaxf(m1v, om1);
        float inv0 = 1.f / (s0*__expf(m0v - M0) + os0*__expf(om0 - M0));
        float inv1 = 1.f / (s1*__expf(m1v - M1) + os1*__expf(om1 - M1));
#pragma unroll
        for (int nt = 0; nt < 4; nt++) {
            int c0 = h*32 + nt*8 + tig*2;
            float a0 = (vv0[nt*2]   > -5e8f) ? __expf(vv0[nt*2]   - M0)*inv0 : 0.f;
            float a1 = (vv0[nt*2+1] > -5e8f) ? __expf(vv0[nt*2+1] - M0)*inv0 : 0.f;
            float b0 = (vv1[nt*2]   > -5e8f) ? __expf(vv1[nt*2]   - M1)*inv1 : 0.f;
            float b1 = (vv1[nt*2+1] > -5e8f) ? __expf(vv1[nt*2+1] - M1)*inv1 : 0.f;
            u32 hi, lo;
            splitp(a0, a1, hi, lo);
            wgH[(m0+gid)*PW + c0/2] = hi; wgL[(m0+gid)*PW + c0/2] = lo;
            splitp(b0, b1, hi, lo);
            wgH[(m0+gid+8)*PW + c0/2] = hi; wgL[(m0+gid+8)*PW + c0/2] = lo;
        }
    }
    BARP(barid);

    // ---- ctx = wgt x win (B via ldmatrix.x4.trans pairs) ----
    {
        float d[4][4] = {};
        u32 aB0[8], aB1[8], bhp[2][4], blp[2][4];
        u32 adA = bWgH + m0*PWB + offA;
        LDSM4(aB0, adA); LDSM4(aB0+4, adA + dP);
#pragma unroll
        for (int ks = 0; ks < 4; ks++) {
            int kB = ks*32;
            u32 adB0 = bWinH + (m0 + ks*16)*PWB + offBT + (h*32)*2;
            u32 adB1 = adB0 + 32;
            LDSM4T(bhp[0], adB0); LDSM4T(blp[0], adB0 + dWin);
            LDSM4T(bhp[1], adB1); LDSM4T(blp[1], adB1 + dWin);
            u32* cur = (ks & 1) ? aB1 : aB0;
            if (ks < 3) {
                u32* nxt = (ks & 1) ? aB0 : aB1;
                u32 adN = adA + kB + 32;
                LDSM4(nxt, adN); LDSM4(nxt+4, adN + dP);
            }
#pragma unroll
            for (int p = 0; p < 2; p++) {
                mma3(d[p*2],   cur, cur+4, bhp[p],   blp[p]);
                mma3(d[p*2+1], cur, cur+4, bhp[p]+2, blp[p]+2);
            }
        }
#pragma unroll
        for (int nt = 0; nt < 4; nt++) {
            int c0 = h*32 + nt*8 + tig*2;
            u32 hi, lo;
            splitp(d[nt][0], d[nt][1], hi, lo);
            uH[(m0+gid)*PW + c0/2] = hi; uL[(m0+gid)*PW + c0/2] = lo;
            splitp(d[nt][2], d[nt][3], hi, lo);
            uH[(m0+gid+8)*PW + c0/2] = hi; uL[(m0+gid+8)*PW + c0/2] = lo;
        }
    }
    BARP(barid);

    // ---- out = ctx x Wt^T + bt (B fragments straight from global/L2) ----
    {
        const u16* wtHg = g_WtH + al*4096;
        const u16* wtLg = g_WtL + al*4096;
        float d[4][4] = {};
        u32 aa[8];
#pragma unroll
        for (int ks = 0; ks < 4; ks++) {
            int kB = ks*32;
            int kk = ks*16 + tig*2;
            u32 bh[4][2], bl[4][2];
#pragma unroll
            for (int nt = 0; nt < 4; nt++) {
                int n0 = (h*32 + nt*8 + gid)*64;
                bh[nt][0] = *(const u32*)&wtHg[n0 + kk];
                bh[nt][1] = *(const u32*)&wtHg[n0 + kk + 8];
                bl[nt][0] = *(const u32*)&wtLg[n0 + kk];
                bl[nt][1] = *(const u32*)&wtLg[n0 + kk + 8];
            }
            u32 adA = bUH + m0*PWB + offA + kB;
            LDSM4(aa, adA); LDSM4(aa+4, adA + dP);
#pragma unroll
            for (int nt = 0; nt < 4; nt++)
                mma3(d[nt], aa, aa+4, bh[nt], bl[nt]);
        }
#pragma unroll
        for (int nt = 0; nt < 4; nt++) {
            int c0 = h*32 + nt*8 + tig*2;
            int q0 = m0 + gid, q1 = m0 + gid + 8;
            size_t i0 = ((((size_t)b*2048 + s0 + q0)*4 + a)*4 + l)*64 + c0;
            size_t i1 = ((((size_t)b*2048 + s0 + q1)*4 + a)*4 + l)*64 + c0;
            *(float2*)&out[i0] = make_float2(d[nt][0] + sBt[c0], d[nt][1] + sBt[c0+1]);
            *(float2*)&out[i1] = make_float2(d[nt][2] + sBt[c0], d[nt][3] + sBt[c0+1]);
        }
    }
}

#define SMEM_BYTES ((112*PW*2 + 64*PW*6 + 112 + 64 + 64 + 256) * 4)

extern "C" void kernel_launch(void* const* d_in, const int* in_sizes, int n_in,
                              void* d_out, int out_size) {
    (void)in_sizes; (void)n_in; (void)out_size;
    const float* X  = (const float*)d_in[0];
    const float* Wq = (const float*)d_in[1];
    const float* bq = (const float*)d_in[2];
    const float* Wk = (const float*)d_in[3];
    const float* Wt = (const float*)d_in[5];
    const float* bt = (const float*)d_in[6];
    float* out = (float*)d_out;
    cudaFuncSetAttribute(attn_kernel, cudaFuncAttributeMaxDynamicSharedMemorySize, SMEM_BYTES);
    precompute_kernel<<<dim3(16,4), 256>>>(Wq, bq, Wk, Wt);
    attn_kernel<<<2048, 256, SMEM_BYTES>>>(X, bt, out);
}

// round 16
// speedup vs baseline: 1.5399x; 1.5399x over previous
#include <cuda_runtime.h>
#include <cuda_bf16.h>
#include <cstdint>
typedef unsigned short u16;
typedef uint32_t u32;

#define KH 20
#define PW 36            // plane pitch in u32
#define PWB 144          // plane pitch in bytes

__device__ u16 g_Ct[16*4096];   // fp16 hi, [al][fo][fi]
__device__ u16 g_Wt[16*4096];   // fp16 hi, [al][g][f]
__device__ float g_cb[16*64];

__device__ __forceinline__ u32 h2(float a, float b){  // pack a->lo16, b->hi16 (fp16)
    u32 r; asm("cvt.rn.f16x2.f32 %0, %1, %2;" : "=r"(r) : "f"(b), "f"(a)); return r;
}
__device__ __forceinline__ void splitp(float a, float b, u32& hi, u32& lo){
    hi = h2(a, b);
    float ha, hb;
    asm("{.reg .b16 x, y;\n\t mov.b32 {x, y}, %2;\n\t cvt.f32.f16 %0, x;\n\t cvt.f32.f16 %1, y;}\n\t"
        : "=f"(ha), "=f"(hb) : "r"(hi));
    lo = h2(a - ha, b - hb);
}
__device__ __forceinline__ u16 f16s(float v){
    return (u16)(h2(v, 0.f) & 0xFFFFu);
}
__device__ __forceinline__ u32 s2u(const void* p){
    u32 a; asm("{ .reg .u64 t; cvta.to.shared.u64 t, %1; cvt.u32.u64 %0, t; }" : "=r"(a) : "l"(p));
    return a;
}
#define BARP(id) asm volatile("bar.sync %0, 64;" :: "r"(id) : "memory")
#define MMAH(d, a, b) asm volatile( \
  "mma.sync.aligned.m16n8k16.row.col.f32.f16.f16.f32 " \
  "{%0,%1,%2,%3},{%4,%5,%6,%7},{%8,%9},{%0,%1,%2,%3};" \
  : "+f"((d)[0]),"+f"((d)[1]),"+f"((d)[2]),"+f"((d)[3]) \
  : "r"((a)[0]),"r"((a)[1]),"r"((a)[2]),"r"((a)[3]),"r"((b)[0]),"r"((b)[1]))
__device__ __forceinline__ void mma2(float* d, const u32* ah, const u32* al, const u32* bh){
    MMAH(d, ah, bh); MMAH(d, al, bh);
}
#define LDSM4(r, ad) asm volatile("ldmatrix.sync.aligned.m8n8.x4.shared.b16 {%0,%1,%2,%3}, [%4];" \
    : "=r"((r)[0]),"=r"((r)[1]),"=r"((r)[2]),"=r"((r)[3]) : "r"(ad))
#define LDSM2(r, ad) asm volatile("ldmatrix.sync.aligned.m8n8.x2.shared.b16 {%0,%1}, [%2];" \
    : "=r"((r)[0]),"=r"((r)[1]) : "r"(ad))
#define LDSM4T(r, ad) asm volatile("ldmatrix.sync.aligned.m8n8.x4.trans.shared.b16 {%0,%1,%2,%3}, [%4];" \
    : "=r"((r)[0]),"=r"((r)[1]),"=r"((r)[2]),"=r"((r)[3]) : "r"(ad))

// ---------------- precompute: grid (16, 4) ----------------
__global__ __launch_bounds__(256) void precompute_kernel(
    const float* __restrict__ Wq, const float* __restrict__ bq,
    const float* __restrict__ Wk, const float* __restrict__ Wt)
{
    __shared__ float sWq[64][65], sWk[64][65], sbq[64];
    int al = blockIdx.x, y = blockIdx.y;
    int a = al >> 2, l = al & 3;
    size_t wb = ((size_t)(7 + a) * 5 + l) * 4096;
    size_t bb = ((size_t)(7 + a) * 5 + l) * 64;
    int t = threadIdx.x;
    for (int i = t; i < 4096; i += 256) {
        sWq[i >> 6][i & 63] = Wq[wb + i];
        sWk[i >> 6][i & 63] = Wk[wb + i];
    }
#pragma unroll
    for (int it = 0; it < 4; it++) {
        int i = y*1024 + it*256 + t;
        g_Wt[al*4096 + i] = f16s(Wt[wb + i]);
    }
    if (t < 64) sbq[t] = bq[bb + t];
    __syncthreads();
    int tf = t & 15, fr = t >> 4;
    int fi = y*16 + fr;
    float acc[4] = {};
    for (int g = 0; g < 64; g++) {
        float qv = sWq[g][fi];
#pragma unroll
        for (int j = 0; j < 4; j++) acc[j] += qv * sWk[g][tf*4 + j];
    }
#pragma unroll
    for (int j = 0; j < 4; j++)
        g_Ct[al*4096 + (tf*4+j)*64 + fi] = f16s(acc[j]);
    if (y == 0 && t < 64) {
        float s = 0.f;
        for (int g = 0; g < 64; g++) s += sbq[g] * sWk[g][t];
        g_cb[al*64 + t] = s;
    }
}

// ---------------- fused attention ----------------
__global__ __launch_bounds__(256, 2) void attn_kernel(
    const float* __restrict__ X, const float* __restrict__ bt,
    float* __restrict__ out)
{
    extern __shared__ u32 sm[];
    u32* winH = sm;
    u32* winL = winH + 112*PW;
    u32* ctH  = winL + 112*PW;         // C^T hi plane only (B operand)
    u32* wtH  = ctH + 64*PW;           // Wt hi plane only (B operand)
    u32* uH   = wtH + 64*PW;           // U planes, later ctx
    u32* uL   = uH + 64*PW;
    u32* wgH  = uL + 64*PW;            // wgt planes
    u32* wgL  = wgH + 64*PW;
    float* sFlag = (float*)(wgL + 64*PW);  // 112
    float* sBt   = sFlag + 112;            // 64
    float* scb   = sBt + 64;               // 64
    float* redM  = scb + 64;               // 128 (row*2 + h)
    float* redS  = redM + 128;             // 128

    int bx = blockIdx.x;
    int st = bx & 31, b = (bx >> 5) & 3, al = bx >> 7;
    int a = al >> 2, l = al & 3;
    int s0 = st * 64;
    int t = threadIdx.x;
    int lane = t & 31;
    int gid = lane >> 2, tig = lane & 3;
    int w = t >> 5, mb = w & 3, h = w >> 2;
    int m0 = mb * 16;
    int barid = mb + 1;

    u32 bWinH = s2u(winH), bCtH = s2u(ctH), bWtH = s2u(wtH), bUH = s2u(uH), bWgH = s2u(wgH);
    const u32 dWin = 112*PWB, dP = 64*PWB;

    const u32 offA  = (lane & 15)*PWB + ((lane >> 4) << 4);
    const u32 offBP = ((lane & 7) + ((lane & 16) >> 1))*PWB + ((lane & 8) << 1);
    const u32 offBS = (lane & 7)*PWB + ((lane & 8) << 1);
    const u32 offBT = (lane & 15)*PWB + (((lane & 16) >> 1) << 1);

    // ---- window load (fp16 dual planes) ----
#pragma unroll
    for (int it = 0; it < 7; it++) {
        int q = t + it*256;
        int r = q >> 4, c4 = q & 15;
        int sg = s0 - KH + r;
        float4 v = make_float4(0.f, 0.f, 0.f, 0.f);
        if (sg >= 0 && sg < 2048)
            v = *(const float4*)&X[(((size_t)b*2048 + sg)*4 + a)*64 + c4*4];
        u32 h01, l01, h23, l23;
        splitp(v.x, v.y, h01, l01);
        splitp(v.z, v.w, h23, l23);
        winH[r*PW + c4*2] = h01; winH[r*PW + c4*2 + 1] = h23;
        winL[r*PW + c4*2] = l01; winL[r*PW + c4*2 + 1] = l23;
        bool nz = (v.x != 0.f) | (v.y != 0.f) | (v.z != 0.f) | (v.w != 0.f);
        u32 m = __ballot_sync(0xFFFFFFFFu, nz);
        if (lane == 0)  sFlag[r] = (m & 0xFFFFu) ? 1.f : 0.f;
        if (lane == 16) sFlag[r] = (m >> 16)     ? 1.f : 0.f;
    }
    const u32* gCt = (const u32*)g_Ct + al*2048;
    const u32* gWt = (const u32*)g_Wt + al*2048;
#pragma unroll
    for (int it = 0; it < 8; it++) {
        int q = t + it*256;
        int r = q >> 5, c = q & 31;
        ctH[r*PW + c] = gCt[q];
        wtH[r*PW + c] = gWt[q];
    }
    if (t < 64) {
        scb[t] = g_cb[al*64 + t];
        sBt[t] = bt[((7 + a)*5 + l)*64 + t];
    }
    __syncthreads();   // only full-CTA barrier; everything after is pair-local

    // ---- U = Xc*C + cb ----
    {
        float d[4][4] = {};
        u32 aB0[8], aB1[8], bhp[2][4];
        u32 adA = bWinH + (KH + m0)*PWB + offA;
        LDSM4(aB0, adA); LDSM4(aB0+4, adA + dWin);
#pragma unroll
        for (int ks = 0; ks < 4; ks++) {
            int kB = ks*32;
            u32 adB0 = bCtH + (h*32)*PWB + offBP + kB;
            u32 adB1 = adB0 + 16*PWB;
            LDSM4(bhp[0], adB0);
            LDSM4(bhp[1], adB1);
            u32* cur = (ks & 1) ? aB1 : aB0;
            if (ks < 3) {
                u32* nxt = (ks & 1) ? aB0 : aB1;
                u32 adN = adA + kB + 32;
                LDSM4(nxt, adN); LDSM4(nxt+4, adN + dWin);
            }
#pragma unroll
            for (int p = 0; p < 2; p++) {
                mma2(d[p*2],   cur, cur+4, bhp[p]);
                mma2(d[p*2+1], cur, cur+4, bhp[p]+2);
            }
        }
#pragma unroll
        for (int nt = 0; nt < 4; nt++) {
            int c0 = h*32 + nt*8 + tig*2;
            float cb0 = scb[c0], cb1 = scb[c0+1];
            u32 hi, lo;
            splitp(d[nt][0] + cb0, d[nt][1] + cb1, hi, lo);
            uH[(m0+gid)*PW + c0/2] = hi; uL[(m0+gid)*PW + c0/2] = lo;
            splitp(d[nt][2] + cb0, d[nt][3] + cb1, hi, lo);
            uH[(m0+gid+8)*PW + c0/2] = hi; uL[(m0+gid+8)*PW + c0/2] = lo;
        }
    }
    BARP(barid);

    // ---- scores (kept in registers) + fragment softmax -> wgt planes ----
    {
        float d[4][4] = {};
        u32 aB0[8], aB1[8], bhp[2][4];
        u32 adA = bUH + m0*PWB + offA;
        LDSM4(aB0, adA); LDSM4(aB0+4, adA + dP);
#pragma unroll
        for (int ks = 0; ks < 4; ks++) {
            int kB = ks*32;
            u32 adB0 = bWinH + (m0 + h*32)*PWB + offBP + kB;
            LDSM4(bhp[0], adB0);
            if (h == 0) {
                u32 adB1 = adB0 + 16*PWB;
                LDSM4(bhp[1], adB1);
            } else {
                u32 adB1 = bWinH + (m0 + 48)*PWB + offBS + kB;
                LDSM2(bhp[1], adB1);
            }
            u32* cur = (ks & 1) ? aB1 : aB0;
            if (ks < 3) {
                u32* nxt = (ks & 1) ? aB0 : aB1;
                u32 adN = adA + kB + 32;
                LDSM4(nxt, adN); LDSM4(nxt+4, adN + dP);
            }
            mma2(d[0], cur, cur+4, bhp[0]);
            mma2(d[1], cur, cur+4, bhp[0]+2);
            mma2(d[2], cur, cur+4, bhp[1]);
            if (h == 0) mma2(d[3], cur, cur+4, bhp[1]+2);
        }
        int nts = (h == 0) ? 4 : 3;
        float vv0[8], vv1[8];
        float m0v = -1e30f, m1v = -1e30f;
#pragma unroll
        for (int nt = 0; nt < 4; nt++) {
#pragma unroll
            for (int hf = 0; hf < 2; hf++) {
                int c = h*32 + nt*8 + tig*2 + hf;
                float v0 = -1e9f, v1 = -1e9f;
                if (nt < nts) {
                    float fl = sFlag[m0 + c];
                    v0 = d[nt][hf]   * 0.125f;
                    v1 = d[nt][2+hf] * 0.125f;
                    if (fl == 0.f) { v0 = -1e9f; v1 = -1e9f; }
                    if (c < gid   || c > gid + 40) v0 = -1e9f;
                    if (c < gid+8 || c > gid + 48) v1 = -1e9f;
                }
                vv0[nt*2+hf] = v0; vv1[nt*2+hf] = v1;
                m0v = fmaxf(m0v, v0); m1v = fmaxf(m1v, v1);
            }
        }
        m0v = fmaxf(m0v, __shfl_xor_sync(0xFFFFFFFFu, m0v, 1));
        m0v = fmaxf(m0v, __shfl_xor_sync(0xFFFFFFFFu, m0v, 2));
        m1v = fmaxf(m1v, __shfl_xor_sync(0xFFFFFFFFu, m1v, 1));
        m1v = fmaxf(m1v, __shfl_xor_sync(0xFFFFFFFFu, m1v, 2));
        float s0 = 0.f, s1 = 0.f;
#pragma unroll
        for (int i = 0; i < 8; i++) {
            s0 += __expf(vv0[i] - m0v);
            s1 += __expf(vv1[i] - m1v);
        }
        s0 += __shfl_xor_sync(0xFFFFFFFFu, s0, 1);
        s0 += __shfl_xor_sync(0xFFFFFFFFu, s0, 2);
        s1 += __shfl_xor_sync(0xFFFFFFFFu, s1, 1);
        s1 += __shfl_xor_sync(0xFFFFFFFFu, s1, 2);
        if (tig == 0) {
            redM[(m0+gid)*2 + h]   = m0v; redS[(m0+gid)*2 + h]   = s0;
            redM[(m0+gid+8)*2 + h] = m1v; redS[(m0+gid+8)*2 + h] = s1;
        }
        BARP(barid);
        float om0 = redM[(m0+gid)*2 + (1^h)],   os0 = redS[(m0+gid)*2 + (1^h)];
        float om1 = redM[(m0+gid+8)*2 + (1^h)], os1 = redS[(m0+gid+8)*2 + (1^h)];
        float M0 = fmaxf(m0v, om0);
        float M1 = fmaxf(m1v, om1);
        float inv0 = 1.f / (s0*__expf(m0v - M0) + os0*__expf(om0 - M0));
        float inv1 = 1.f / (s1*__expf(m1v - M1) + os1*__expf(om1 - M1));
#pragma unroll
        for (int nt = 0; nt < 4; nt++) {
            int c0 = h*32 + nt*8 + tig*2;
            float a0 = (vv0[nt*2]   > -5e8f) ? __expf(vv0[nt*2]   - M0)*inv0 : 0.f;
            float a1 = (vv0[nt*2+1] > -5e8f) ? __expf(vv0[nt*2+1] - M0)*inv0 : 0.f;
            float b0 = (vv1[nt*2]   > -5e8f) ? __expf(vv1[nt*2]   - M1)*inv1 : 0.f;
            float b1 = (vv1[nt*2+1] > -5e8f) ? __expf(vv1[nt*2+1] - M1)*inv1 : 0.f;
            u32 hi, lo;
            splitp(a0, a1, hi, lo);
            wgH[(m0+gid)*PW + c0/2] = hi; wgL[(m0+gid)*PW + c0/2] = lo;
            splitp(b0, b1, hi, lo);
            wgH[(m0+gid+8)*PW + c0/2] = hi; wgL[(m0+gid+8)*PW + c0/2] = lo;
        }
    }
    BARP(barid);

    // ---- ctx = wgt x win (B via ldmatrix.x4.trans, hi plane only) ----
    {
        float d[4][4] = {};
        u32 aB0[8], aB1[8], bhp[2][4];
        u32 adA = bWgH + m0*PWB + offA;
        LDSM4(aB0, adA); LDSM4(aB0+4, adA + dP);
#pragma unroll
        for (int ks = 0; ks < 4; ks++) {
            int kB = ks*32;
            u32 adB0 = bWinH + (m0 + ks*16)*PWB + offBT + (h*32)*2;
            u32 adB1 = adB0 + 32;
            LDSM4T(bhp[0], adB0);
            LDSM4T(bhp[1], adB1);
            u32* cur = (ks & 1) ? aB1 : aB0;
            if (ks < 3) {
                u32* nxt = (ks & 1) ? aB0 : aB1;
                u32 adN = adA + kB + 32;
                LDSM4(nxt, adN); LDSM4(nxt+4, adN + dP);
            }
#pragma unroll
            for (int p = 0; p < 2; p++) {
                mma2(d[p*2],   cur, cur+4, bhp[p]);
                mma2(d[p*2+1], cur, cur+4, bhp[p]+2);
            }
        }
#pragma unroll
        for (int nt = 0; nt < 4; nt++) {
            int c0 = h*32 + nt*8 + tig*2;
            u32 hi, lo;
            splitp(d[nt][0], d[nt][1], hi, lo);
            uH[(m0+gid)*PW + c0/2] = hi; uL[(m0+gid)*PW + c0/2] = lo;
            splitp(d[nt][2], d[nt][3], hi, lo);
            uH[(m0+gid+8)*PW + c0/2] = hi; uL[(m0+gid+8)*PW + c0/2] = lo;
        }
    }
    BARP(barid);

    // ---- out = ctx x Wt^T + bt (B from wt smem, hi plane only) ----
    {
        float d[4][4] = {};
        u32 aB0[8], aB1[8], bhp[2][4];
        u32 adA = bUH + m0*PWB + offA;
        LDSM4(aB0, adA); LDSM4(aB0+4, adA + dP);
#pragma unroll
        for (int ks = 0; ks < 4; ks++) {
            int kB = ks*32;
            u32 adB0 = bWtH + (h*32)*PWB + offBP + kB;
            u32 adB1 = adB0 + 16*PWB;
            LDSM4(bhp[0], adB0);
            LDSM4(bhp[1], adB1);
            u32* cur = (ks & 1) ? aB1 : aB0;
            if (ks < 3) {
                u32* nxt = (ks & 1) ? aB0 : aB1;
                u32 adN = adA + kB + 32;
                LDSM4(nxt, adN); LDSM4(nxt+4, adN + dP);
            }
#pragma unroll
            for (int p = 0; p < 2; p++) {
                mma2(d[p*2],   cur, cur+4, bhp[p]);
                mma2(d[p*2+1], cur, cur+4, bhp[p]+2);
            }
        }
#pragma unroll
        for (int nt = 0; nt < 4; nt++) {
            int c0 = h*32 + nt*8 + tig*2;
            int q0 = m0 + gid, q1 = m0 + gid + 8;
            size_t i0 = ((((size_t)b*2048 + s0 + q0)*4 + a)*4 + l)*64 + c0;
            size_t i1 = ((((size_t)b*2048 + s0 + q1)*4 + a)*4 + l)*64 + c0;
            *(float2*)&out[i0] = make_float2(d[nt][0] + sBt[c0], d[nt][1] + sBt[c0+1]);
            *(float2*)&out[i1] = make_float2(d[nt][2] + sBt[c0], d[nt][3] + sBt[c0+1]);
        }
    }
}

#define SMEM_BYTES ((112*PW*2 + 64*PW*6 + 112 + 64 + 64 + 256) * 4)

extern "C" void kernel_launch(void* const* d_in, const int* in_sizes, int n_in,
                              void* d_out, int out_size) {
    (void)in_sizes; (void)n_in; (void)out_size;
    const float* X  = (const float*)d_in[0];
    const float* Wq = (const float*)d_in[1];
    const float* bq = (const float*)d_in[2];
    const float* Wk = (const float*)d_in[3];
    const float* Wt = (const float*)d_in[5];
    const float* bt = (const float*)d_in[6];
    float* out = (float*)d_out;
    cudaFuncSetAttribute(attn_kernel, cudaFuncAttributeMaxDynamicSharedMemorySize, SMEM_BYTES);
    precompute_kernel<<<dim3(16,4), 256>>>(Wq, bq, Wk, Wt);
    attn_kernel<<<2048, 256, SMEM_BYTES>>>(X, bt, out);
}

// round 17
// speedup vs baseline: 1.7150x; 1.1137x over previous
#include <cuda_runtime.h>
#include <cuda_bf16.h>
#include <cstdint>
typedef unsigned short u16;
typedef uint32_t u32;

#define KH 20
#define PW 36            // plane pitch in u32
#define PWB 144          // plane pitch in bytes

__device__ u16 g_Ct[16*4096];   // fp16 hi, [al][fo][fi]
__device__ u16 g_Wt[16*4096];   // fp16 hi, [al][g][f]
__device__ float g_cb[16*64];

__device__ __forceinline__ u32 h2(float a, float b){  // pack a->lo16, b->hi16 (fp16)
    u32 r; asm("cvt.rn.f16x2.f32 %0, %1, %2;" : "=r"(r) : "f"(b), "f"(a)); return r;
}
__device__ __forceinline__ void splitp(float a, float b, u32& hi, u32& lo){
    hi = h2(a, b);
    float ha, hb;
    asm("{.reg .b16 x, y;\n\t mov.b32 {x, y}, %2;\n\t cvt.f32.f16 %0, x;\n\t cvt.f32.f16 %1, y;}\n\t"
        : "=f"(ha), "=f"(hb) : "r"(hi));
    lo = h2(a - ha, b - hb);
}
__device__ __forceinline__ u16 f16s(float v){
    return (u16)(h2(v, 0.f) & 0xFFFFu);
}
__device__ __forceinline__ u32 s2u(const void* p){
    u32 a; asm("{ .reg .u64 t; cvta.to.shared.u64 t, %1; cvt.u32.u64 %0, t; }" : "=r"(a) : "l"(p));
    return a;
}
#define BARP(id) asm volatile("bar.sync %0, 64;" :: "r"(id) : "memory")
#define MMAH(d, a, b) asm volatile( \
  "mma.sync.aligned.m16n8k16.row.col.f32.f16.f16.f32 " \
  "{%0,%1,%2,%3},{%4,%5,%6,%7},{%8,%9},{%0,%1,%2,%3};" \
  : "+f"((d)[0]),"+f"((d)[1]),"+f"((d)[2]),"+f"((d)[3]) \
  : "r"((a)[0]),"r"((a)[1]),"r"((a)[2]),"r"((a)[3]),"r"((b)[0]),"r"((b)[1]))
__device__ __forceinline__ void mma2(float* d, const u32* ah, const u32* al, const u32* bh){
    MMAH(d, ah, bh); MMAH(d, al, bh);
}
#define LDSM4(r, ad) asm volatile("ldmatrix.sync.aligned.m8n8.x4.shared.b16 {%0,%1,%2,%3}, [%4];" \
    : "=r"((r)[0]),"=r"((r)[1]),"=r"((r)[2]),"=r"((r)[3]) : "r"(ad))
#define LDSM2(r, ad) asm volatile("ldmatrix.sync.aligned.m8n8.x2.shared.b16 {%0,%1}, [%2];" \
    : "=r"((r)[0]),"=r"((r)[1]) : "r"(ad))
#define LDSM4T(r, ad) asm volatile("ldmatrix.sync.aligned.m8n8.x4.trans.shared.b16 {%0,%1,%2,%3}, [%4];" \
    : "=r"((r)[0]),"=r"((r)[1]),"=r"((r)[2]),"=r"((r)[3]) : "r"(ad))

// ---------------- precompute: grid (16, 4) ----------------
__global__ __launch_bounds__(256) void precompute_kernel(
    const float* __restrict__ Wq, const float* __restrict__ bq,
    const float* __restrict__ Wk, const float* __restrict__ Wt)
{
    __shared__ float sWq[64][65], sWk[64][65], sbq[64];
    int al = blockIdx.x, y = blockIdx.y;
    int a = al >> 2, l = al & 3;
    size_t wb = ((size_t)(7 + a) * 5 + l) * 4096;
    size_t bb = ((size_t)(7 + a) * 5 + l) * 64;
    int t = threadIdx.x;
    for (int i = t; i < 4096; i += 256) {
        sWq[i >> 6][i & 63] = Wq[wb + i];
        sWk[i >> 6][i & 63] = Wk[wb + i];
    }
#pragma unroll
    for (int it = 0; it < 4; it++) {
        int i = y*1024 + it*256 + t;
        g_Wt[al*4096 + i] = f16s(Wt[wb + i]);
    }
    if (t < 64) sbq[t] = bq[bb + t];
    __syncthreads();
    int tf = t & 15, fr = t >> 4;
    int fi = y*16 + fr;
    float acc[4] = {};
    for (int g = 0; g < 64; g++) {
        float qv = sWq[g][fi];
#pragma unroll
        for (int j = 0; j < 4; j++) acc[j] += qv * sWk[g][tf*4 + j];
    }
#pragma unroll
    for (int j = 0; j < 4; j++)
        g_Ct[al*4096 + (tf*4+j)*64 + fi] = f16s(acc[j]);
    if (y == 0 && t < 64) {
        float s = 0.f;
        for (int g = 0; g < 64; g++) s += sbq[g] * sWk[g][t];
        g_cb[al*64 + t] = s;
    }
}

// ---------------- fused attention ----------------
__global__ __launch_bounds__(256, 3) void attn_kernel(
    const float* __restrict__ X, const float* __restrict__ bt,
    float* __restrict__ out)
{
    extern __shared__ u32 sm[];
    u32* winH = sm;
    u32* winL = winH + 112*PW;
    u32* ctH  = winL + 112*PW;         // C^T hi plane only (B operand)
    u32* wtH  = ctH + 64*PW;           // Wt hi plane only (B operand)
    u32* uH   = wtH + 64*PW;           // U planes -> wgt -> ctx (pair-row-partitioned)
    u32* uL   = uH + 64*PW;
    float* sFlag = (float*)(uL + 64*PW);   // 112
    float* sBt   = sFlag + 112;            // 64
    float* scb   = sBt + 64;               // 64
    float* redM  = scb + 64;               // 128 (row*2 + h)
    float* redS  = redM + 128;             // 128

    int bx = blockIdx.x;
    int st = bx & 31, b = (bx >> 5) & 3, al = bx >> 7;
    int a = al >> 2, l = al & 3;
    int s0 = st * 64;
    int t = threadIdx.x;
    int lane = t & 31;
    int gid = lane >> 2, tig = lane & 3;
    int w = t >> 5, mb = w & 3, h = w >> 2;
    int m0 = mb * 16;
    int barid = mb + 1;

    u32 bWinH = s2u(winH), bCtH = s2u(ctH), bWtH = s2u(wtH), bUH = s2u(uH);
    const u32 dWin = 112*PWB, dP = 64*PWB;

    const u32 offA  = (lane & 15)*PWB + ((lane >> 4) << 4);
    const u32 offBP = ((lane & 7) + ((lane & 16) >> 1))*PWB + ((lane & 8) << 1);
    const u32 offBS = (lane & 7)*PWB + ((lane & 8) << 1);
    const u32 offBT = (lane & 15)*PWB + (((lane & 16) >> 1) << 1);

    // ---- window load (fp16 dual planes) ----
#pragma unroll
    for (int it = 0; it < 7; it++) {
        int q = t + it*256;
        int r = q >> 4, c4 = q & 15;
        int sg = s0 - KH + r;
        float4 v = make_float4(0.f, 0.f, 0.f, 0.f);
        if (sg >= 0 && sg < 2048)
            v = *(const float4*)&X[(((size_t)b*2048 + sg)*4 + a)*64 + c4*4];
        u32 h01, l01, h23, l23;
        splitp(v.x, v.y, h01, l01);
        splitp(v.z, v.w, h23, l23);
        winH[r*PW + c4*2] = h01; winH[r*PW + c4*2 + 1] = h23;
        winL[r*PW + c4*2] = l01; winL[r*PW + c4*2 + 1] = l23;
        bool nz = (v.x != 0.f) | (v.y != 0.f) | (v.z != 0.f) | (v.w != 0.f);
        u32 m = __ballot_sync(0xFFFFFFFFu, nz);
        if (lane == 0)  sFlag[r] = (m & 0xFFFFu) ? 1.f : 0.f;
        if (lane == 16) sFlag[r] = (m >> 16)     ? 1.f : 0.f;
    }
    const u32* gCt = (const u32*)g_Ct + al*2048;
    const u32* gWt = (const u32*)g_Wt + al*2048;
#pragma unroll
    for (int it = 0; it < 8; it++) {
        int q = t + it*256;
        int r = q >> 5, c = q & 31;
        ctH[r*PW + c] = gCt[q];
        wtH[r*PW + c] = gWt[q];
    }
    if (t < 64) {
        scb[t] = g_cb[al*64 + t];
        sBt[t] = bt[((7 + a)*5 + l)*64 + t];
    }
    __syncthreads();   // only full-CTA barrier; everything after is pair-local

    // ---- U = Xc*C + cb ----
    {
        float d[4][4] = {};
        u32 aB0[8], aB1[8], bhp[2][4];
        u32 adA = bWinH + (KH + m0)*PWB + offA;
        LDSM4(aB0, adA); LDSM4(aB0+4, adA + dWin);
#pragma unroll
        for (int ks = 0; ks < 4; ks++) {
            int kB = ks*32;
            u32 adB0 = bCtH + (h*32)*PWB + offBP + kB;
            u32 adB1 = adB0 + 16*PWB;
            LDSM4(bhp[0], adB0);
            LDSM4(bhp[1], adB1);
            u32* cur = (ks & 1) ? aB1 : aB0;
            if (ks < 3) {
                u32* nxt = (ks & 1) ? aB0 : aB1;
                u32 adN = adA + kB + 32;
                LDSM4(nxt, adN); LDSM4(nxt+4, adN + dWin);
            }
#pragma unroll
            for (int p = 0; p < 2; p++) {
                mma2(d[p*2],   cur, cur+4, bhp[p]);
                mma2(d[p*2+1], cur, cur+4, bhp[p]+2);
            }
        }
#pragma unroll
        for (int nt = 0; nt < 4; nt++) {
            int c0 = h*32 + nt*8 + tig*2;
            float cb0 = scb[c0], cb1 = scb[c0+1];
            u32 hi, lo;
            splitp(d[nt][0] + cb0, d[nt][1] + cb1, hi, lo);
            uH[(m0+gid)*PW + c0/2] = hi; uL[(m0+gid)*PW + c0/2] = lo;
            splitp(d[nt][2] + cb0, d[nt][3] + cb1, hi, lo);
            uH[(m0+gid+8)*PW + c0/2] = hi; uL[(m0+gid+8)*PW + c0/2] = lo;
        }
    }
    BARP(barid);

    // ---- scores (registers) + fragment softmax -> wgt overlaid into U planes ----
    {
        float d[4][4] = {};
        u32 aB0[8], aB1[8], bhp[2][4];
        u32 adA = bUH + m0*PWB + offA;
        LDSM4(aB0, adA); LDSM4(aB0+4, adA + dP);
#pragma unroll
        for (int ks = 0; ks < 4; ks++) {
            int kB = ks*32;
            u32 adB0 = bWinH + (m0 + h*32)*PWB + offBP + kB;
            LDSM4(bhp[0], adB0);
            if (h == 0) {
                u32 adB1 = adB0 + 16*PWB;
                LDSM4(bhp[1], adB1);
            } else {
                u32 adB1 = bWinH + (m0 + 48)*PWB + offBS + kB;
                LDSM2(bhp[1], adB1);
            }
            u32* cur = (ks & 1) ? aB1 : aB0;
            if (ks < 3) {
                u32* nxt = (ks & 1) ? aB0 : aB1;
                u32 adN = adA + kB + 32;
                LDSM4(nxt, adN); LDSM4(nxt+4, adN + dP);
            }
            mma2(d[0], cur, cur+4, bhp[0]);
            mma2(d[1], cur, cur+4, bhp[0]+2);
            mma2(d[2], cur, cur+4, bhp[1]);
            if (h == 0) mma2(d[3], cur, cur+4, bhp[1]+2);
        }
        int nts = (h == 0) ? 4 : 3;
        float vv0[8], vv1[8];
        float m0v = -1e30f, m1v = -1e30f;
#pragma unroll
        for (int nt = 0; nt < 4; nt++) {
#pragma unroll
            for (int hf = 0; hf < 2; hf++) {
                int c = h*32 + nt*8 + tig*2 + hf;
                float v0 = -1e9f, v1 = -1e9f;
                if (nt < nts) {
                    float fl = sFlag[m0 + c];
                    v0 = d[nt][hf]   * 0.125f;
                    v1 = d[nt][2+hf] * 0.125f;
                    if (fl == 0.f) { v0 = -1e9f; v1 = -1e9f; }
                    if (c < gid   || c > gid + 40) v0 = -1e9f;
                    if (c < gid+8 || c > gid + 48) v1 = -1e9f;
                }
                vv0[nt*2+hf] = v0; vv1[nt*2+hf] = v1;
                m0v = fmaxf(m0v, v0); m1v = fmaxf(m1v, v1);
            }
        }
        m0v = fmaxf(m0v, __shfl_xor_sync(0xFFFFFFFFu, m0v, 1));
        m0v = fmaxf(m0v, __shfl_xor_sync(0xFFFFFFFFu, m0v, 2));
        m1v = fmaxf(m1v, __shfl_xor_sync(0xFFFFFFFFu, m1v, 1));
        m1v = fmaxf(m1v, __shfl_xor_sync(0xFFFFFFFFu, m1v, 2));
        float s0 = 0.f, s1 = 0.f;
#pragma unroll
        for (int i = 0; i < 8; i++) {
            s0 += __expf(vv0[i] - m0v);
            s1 += __expf(vv1[i] - m1v);
        }
        s0 += __shfl_xor_sync(0xFFFFFFFFu, s0, 1);
        s0 += __shfl_xor_sync(0xFFFFFFFFu, s0, 2);
        s1 += __shfl_xor_sync(0xFFFFFFFFu, s1, 1);
        s1 += __shfl_xor_sync(0xFFFFFFFFu, s1, 2);
        if (tig == 0) {
            redM[(m0+gid)*2 + h]   = m0v; redS[(m0+gid)*2 + h]   = s0;
            redM[(m0+gid+8)*2 + h] = m1v; redS[(m0+gid+8)*2 + h] = s1;
        }
        BARP(barid);   // orders partner's U-plane A reads before the wgt overlay below
        float om0 = redM[(m0+gid)*2 + (1^h)],   os0 = redS[(m0+gid)*2 + (1^h)];
        float om1 = redM[(m0+gid+8)*2 + (1^h)], os1 = redS[(m0+gid+8)*2 + (1^h)];
        float M0 = fmaxf(m0v, om0);
        float M1 = fmaxf(m1v, om1);
        float inv0 = 1.f / (s0*__expf(m0v - M0) + os0*__expf(om0 - M0));
        float inv1 = 1.f / (s1*__expf(m1v - M1) + os1*__expf(om1 - M1));
#pragma unroll
        for (int nt = 0; nt < 4; nt++) {
            int c0 = h*32 + nt*8 + tig*2;
            float a0 = (vv0[nt*2]   > -5e8f) ? __expf(vv0[nt*2]   - M0)*inv0 : 0.f;
            float a1 = (vv0[nt*2+1] > -5e8f) ? __expf(vv0[nt*2+1] - M0)*inv0 : 0.f;
            float b0 = (vv1[nt*2]   > -5e8f) ? __expf(vv1[nt*2]   - M1)*inv1 : 0.f;
            float b1 = (vv1[nt*2+1] > -5e8f) ? __expf(vv1[nt*2+1] - M1)*inv1 : 0.f;
            u32 hi, lo;
            splitp(a0, a1, hi, lo);
            uH[(m0+gid)*PW + c0/2] = hi; uL[(m0+gid)*PW + c0/2] = lo;
            splitp(b0, b1, hi, lo);
            uH[(m0+gid+8)*PW + c0/2] = hi; uL[(m0+gid+8)*PW + c0/2] = lo;
        }
    }
    BARP(barid);

    // ---- ctx = wgt x win (A from U planes; result overlaid back) ----
    {
        float d[4][4] = {};
        u32 aB0[8], aB1[8], bhp[2][4];
        u32 adA = bUH + m0*PWB + offA;
        LDSM4(aB0, adA); LDSM4(aB0+4, adA + dP);
#pragma unroll
        for (int ks = 0; ks < 4; ks++) {
            int kB = ks*32;
            u32 adB0 = bWinH + (m0 + ks*16)*PWB + offBT + (h*32)*2;
            u32 adB1 = adB0 + 32;
            LDSM4T(bhp[0], adB0);
            LDSM4T(bhp[1], adB1);
            u32* cur = (ks & 1) ? aB1 : aB0;
            if (ks < 3) {
                u32* nxt = (ks & 1) ? aB0 : aB1;
                u32 adN = adA + kB + 32;
                LDSM4(nxt, adN); LDSM4(nxt+4, adN + dP);
            }
#pragma unroll
            for (int p = 0; p < 2; p++) {
                mma2(d[p*2],   cur, cur+4, bhp[p]);
                mma2(d[p*2+1], cur, cur+4, bhp[p]+2);
            }
        }
        BARP(barid);   // partner still reads wgt rows m0..15 as A; wait before overwrite
#pragma unroll
        for (int nt = 0; nt < 4; nt++) {
            int c0 = h*32 + nt*8 + tig*2;
            u32 hi, lo;
            splitp(d[nt][0], d[nt][1], hi, lo);
            uH[(m0+gid)*PW + c0/2] = hi; uL[(m0+gid)*PW + c0/2] = lo;
            splitp(d[nt][2], d[nt][3], hi, lo);
            uH[(m0+gid+8)*PW + c0/2] = hi; uL[(m0+gid+8)*PW + c0/2] = lo;
        }
    }
    BARP(barid);

    // ---- out = ctx x Wt^T + bt (B from wt smem, hi plane only) ----
    {
        float d[4][4] = {};
        u32 aB0[8], aB1[8], bhp[2][4];
        u32 adA = bUH + m0*PWB + offA;
        LDSM4(aB0, adA); LDSM4(aB0+4, adA + dP);
#pragma unroll
        for (int ks = 0; ks < 4; ks++) {
            int kB = ks*32;
            u32 adB0 = bWtH + (h*32)*PWB + offBP + kB;
            u32 adB1 = adB0 + 16*PWB;
            LDSM4(bhp[0], adB0);
            LDSM4(bhp[1], adB1);
            u32* cur = (ks & 1) ? aB1 : aB0;
            if (ks < 3) {
                u32* nxt = (ks & 1) ? aB0 : aB1;
                u32 adN = adA + kB + 32;
                LDSM4(nxt, adN); LDSM4(nxt+4, adN + dP);
            }
#pragma unroll
            for (int p = 0; p < 2; p++) {
                mma2(d[p*2],   cur, cur+4, bhp[p]);
                mma2(d[p*2+1], cur, cur+4, bhp[p]+2);
            }
        }
#pragma unroll
        for (int nt = 0; nt < 4; nt++) {
            int c0 = h*32 + nt*8 + tig*2;
            int q0 = m0 + gid, q1 = m0 + gid + 8;
            size_t i0 = ((((size_t)b*2048 + s0 + q0)*4 + a)*4 + l)*64 + c0;
            size_t i1 = ((((size_t)b*2048 + s0 + q1)*4 + a)*4 + l)*64 + c0;
            *(float2*)&out[i0] = make_float2(d[nt][0] + sBt[c0], d[nt][1] + sBt[c0+1]);
            *(float2*)&out[i1] = make_float2(d[nt][2] + sBt[c0], d[nt][3] + sBt[c0+1]);
        }
    }
}

#define SMEM_BYTES ((112*PW*2 + 64*PW*4 + 112 + 64 + 64 + 256) * 4)

extern "C" void kernel_launch(void* const* d_in, const int* in_sizes, int n_in,
                              void* d_out, int out_size) {
    (void)in_sizes; (void)n_in; (void)out_size;
    const float* X  = (const float*)d_in[0];
    const float* Wq = (const float*)d_in[1];
    const float* bq = (const float*)d_in[2];
    const float* Wk = (const float*)d_in[3];
    const float* Wt = (const float*)d_in[5];
    const float* bt = (const float*)d_in[6];
    float* out = (float*)d_out;
    cudaFuncSetAttribute(attn_kernel, cudaFuncAttributeMaxDynamicSharedMemorySize, SMEM_BYTES);
    precompute_kernel<<<dim3(16,4), 256>>>(Wq, bq, Wk, Wt);
    attn_kernel<<<2048, 256, SMEM_BYTES>>>(X, bt, out);
}